// round 1
// baseline (speedup 1.0000x reference)
#include <cuda_runtime.h>
#include <cuda_bf16.h>
#include <cstdint>
#include <cstdio>

// Problem constants
#define NB   4
#define LSEQ 2048
#define EQ   512
#define ET   512
#define NH   8
#define EH   64
#define NF   8

// Scratch (device globals; allocation-free per harness rules)
__device__ float g_qkv [(size_t)NB * LSEQ * 3 * ET];   // [b, s, 3*512]
__device__ float g_attn[(size_t)NB * NH * LSEQ * EH];  // [b, h, s, 64]
__device__ float g_roll[(size_t)NB * NF * LSEQ * ET];  // [b, n, s, 512]

// ---------------------------------------------------------------------------
// Generic fp32 SGEMM with bias: C[M,N] = A[M,K] @ B[K,N] + bias[N]
// BM=BN=64, BK=16, 256 threads, 4x4 register tile per thread.
// M % 64 == 0, N % 64 == 0, K % 16 == 0 (true for all our calls).
// ---------------------------------------------------------------------------
__global__ __launch_bounds__(256) void sgemm_bias64(
    const float* __restrict__ A, const float* __restrict__ B,
    const float* __restrict__ bias, float* __restrict__ C,
    int M, int N, int K)
{
    __shared__ float As[16][65];  // stored transposed: As[k][m]
    __shared__ float Bs[16][64];

    const int tid = threadIdx.x;
    const int tx = tid & 15;          // 0..15 -> 4 cols each
    const int ty = tid >> 4;          // 0..15 -> 4 rows each
    const int rowBase = blockIdx.y * 64;
    const int colBase = blockIdx.x * 64;

    float acc[4][4] = {};

    for (int k0 = 0; k0 < K; k0 += 16) {
        // Load A tile (64x16) transposed into As[k][m]
        #pragma unroll
        for (int i = tid; i < 64 * 16; i += 256) {
            int r = i >> 4, c = i & 15;
            As[c][r] = A[(size_t)(rowBase + r) * K + k0 + c];
        }
        // Load B tile (16x64)
        #pragma unroll
        for (int i = tid; i < 16 * 64; i += 256) {
            int r = i >> 6, c = i & 63;
            Bs[r][c] = B[(size_t)(k0 + r) * N + colBase + c];
        }
        __syncthreads();

        #pragma unroll
        for (int kk = 0; kk < 16; kk++) {
            float a[4], bv[4];
            #pragma unroll
            for (int i = 0; i < 4; i++) a[i]  = As[kk][ty * 4 + i];
            #pragma unroll
            for (int j = 0; j < 4; j++) bv[j] = Bs[kk][tx * 4 + j];
            #pragma unroll
            for (int i = 0; i < 4; i++)
                #pragma unroll
                for (int j = 0; j < 4; j++)
                    acc[i][j] += a[i] * bv[j];
        }
        __syncthreads();
    }

    #pragma unroll
    for (int i = 0; i < 4; i++) {
        int r = rowBase + ty * 4 + i;
        #pragma unroll
        for (int j = 0; j < 4; j++) {
            int c = colBase + tx * 4 + j;
            C[(size_t)r * N + c] = acc[i][j] + bias[c];
        }
    }
}

// ---------------------------------------------------------------------------
// Causal flash attention, fp32. One block per (q_tile=64, head, batch).
// qkv layout: [b, s, 1536] with q at +h*64, k at +512+h*64, v at +1024+h*64.
// attn out layout: [b, h, s, 64].
// ---------------------------------------------------------------------------
#define NEGINF (-1e30f)

__global__ __launch_bounds__(256) void flash_attn_kernel(float* __restrict__ attn)
{
    extern __shared__ float sm[];
    float* Qs   = sm;                 // 64 x 65
    float* Ks   = Qs + 64 * 65;       // 64 x 65
    float* Vs   = Ks + 64 * 65;       // 64 x 65
    float* Ss   = Vs + 64 * 65;       // 64 x 65 (scores / probs)
    float* mrow = Ss + 64 * 65;       // 64
    float* lrow = mrow + 64;          // 64
    float* srow = lrow + 64;          // 64 (rescale factor)

    const int qt  = blockIdx.x;
    const int h   = blockIdx.y;
    const int b   = blockIdx.z;
    const int tid = threadIdx.x;
    const int tx  = tid & 15;
    const int ty  = tid >> 4;
    const int q0  = qt * 64;

    // Load Q tile
    for (int i = tid; i < 64 * 64; i += 256) {
        int r = i >> 6, d = i & 63;
        Qs[r * 65 + d] = g_qkv[((size_t)(b * LSEQ + q0 + r)) * 1536 + h * 64 + d];
    }
    if (tid < 64) { mrow[tid] = NEGINF; lrow[tid] = 0.f; }

    float acc[4][4] = {};
    __syncthreads();

    for (int kt = 0; kt <= qt; kt++) {
        const int k0 = kt * 64;
        // Load K,V tiles
        for (int i = tid; i < 64 * 64; i += 256) {
            int r = i >> 6, d = i & 63;
            size_t base = ((size_t)(b * LSEQ + k0 + r)) * 1536 + h * 64 + d;
            Ks[r * 65 + d] = g_qkv[base + 512];
            Vs[r * 65 + d] = g_qkv[base + 1024];
        }
        __syncthreads();

        // S = Q @ K^T * scale  (thread: rows ty*4.., cols tx*4..)
        {
            float s[4][4] = {};
            #pragma unroll
            for (int k = 0; k < 64; k++) {
                float a[4], bv[4];
                #pragma unroll
                for (int i = 0; i < 4; i++) a[i]  = Qs[(ty * 4 + i) * 65 + k];
                #pragma unroll
                for (int j = 0; j < 4; j++) bv[j] = Ks[(tx * 4 + j) * 65 + k];
                #pragma unroll
                for (int i = 0; i < 4; i++)
                    #pragma unroll
                    for (int j = 0; j < 4; j++)
                        s[i][j] += a[i] * bv[j];
            }
            const bool diag = (kt == qt);
            #pragma unroll
            for (int i = 0; i < 4; i++) {
                int r = ty * 4 + i;
                #pragma unroll
                for (int j = 0; j < 4; j++) {
                    int c = tx * 4 + j;
                    float v = s[i][j] * 0.125f;
                    if (diag && c > r) v = NEGINF;   // causal within diagonal tile
                    Ss[r * 65 + c] = v;
                }
            }
        }
        __syncthreads();

        // Online softmax row update: one thread per row (tid < 64)
        if (tid < 64) {
            int r = tid;
            float mx = mrow[r];
            #pragma unroll 8
            for (int c = 0; c < 64; c++) mx = fmaxf(mx, Ss[r * 65 + c]);
            float sf = __expf(mrow[r] - mx);
            float sum = 0.f;
            #pragma unroll 8
            for (int c = 0; c < 64; c++) {
                float p = __expf(Ss[r * 65 + c] - mx);
                Ss[r * 65 + c] = p;
                sum += p;
            }
            mrow[r] = mx;
            lrow[r] = lrow[r] * sf + sum;
            srow[r] = sf;
        }
        __syncthreads();

        // acc = acc*sf + P @ V
        {
            float o[4][4] = {};
            #pragma unroll
            for (int k = 0; k < 64; k++) {
                float a[4], bv[4];
                #pragma unroll
                for (int i = 0; i < 4; i++) a[i]  = Ss[(ty * 4 + i) * 65 + k];
                #pragma unroll
                for (int j = 0; j < 4; j++) bv[j] = Vs[k * 65 + tx * 4 + j];
                #pragma unroll
                for (int i = 0; i < 4; i++)
                    #pragma unroll
                    for (int j = 0; j < 4; j++)
                        o[i][j] += a[i] * bv[j];
            }
            #pragma unroll
            for (int i = 0; i < 4; i++) {
                float sf = srow[ty * 4 + i];
                #pragma unroll
                for (int j = 0; j < 4; j++)
                    acc[i][j] = acc[i][j] * sf + o[i][j];
            }
        }
        __syncthreads();
    }

    // Normalize and write attn [b,h,s,64]
    #pragma unroll
    for (int i = 0; i < 4; i++) {
        int r = ty * 4 + i;
        float inv = 1.f / lrow[r];
        #pragma unroll
        for (int j = 0; j < 4; j++) {
            int c = tx * 4 + j;
            attn[(((size_t)(b * NH + h)) * LSEQ + q0 + r) * EH + c] = acc[i][j] * inv;
        }
    }
}

// ---------------------------------------------------------------------------
// Forecast recurrence: x_{n+1} = x_n + x_n @ A,  A = Xi[h] - Xi[h]^T (64x64).
// Writes all 8 states to g_roll[b, n, s, h*64 + e].
// Block: 32 s-rows, 256 threads (thread -> (row = tid/8, 8 cols)).
// ---------------------------------------------------------------------------
__global__ __launch_bounds__(256) void forecast_kernel(const float* __restrict__ Xi)
{
    __shared__ float As[64][64];
    __shared__ float Xs[32][65];

    const int st = blockIdx.x, h = blockIdx.y, b = blockIdx.z;
    const int tid = threadIdx.x;
    const int s0 = st * 32;

    // A = Xi[h] - Xi[h]^T
    for (int i = tid; i < 64 * 64; i += 256) {
        int d = i >> 6, e = i & 63;
        As[d][e] = Xi[h * 4096 + d * 64 + e] - Xi[h * 4096 + e * 64 + d];
    }
    // x0 = attn tile
    for (int i = tid; i < 32 * 64; i += 256) {
        int r = i >> 6, d = i & 63;
        Xs[r][d] = g_attn[(((size_t)(b * NH + h)) * LSEQ + s0 + r) * EH + d];
    }
    __syncthreads();

    const int r  = tid >> 3;        // 0..31
    const int e0 = (tid & 7) * 8;   // 8 output cols per thread

    for (int n = 0; n < NF; n++) {
        float y[8];
        #pragma unroll
        for (int j = 0; j < 8; j++) {
            int e = e0 + j;
            float s = Xs[r][e];
            #pragma unroll 8
            for (int d = 0; d < 64; d++) s += Xs[r][d] * As[d][e];
            y[j] = s;
        }
        __syncthreads();
        size_t base = (((size_t)(b * NF + n)) * LSEQ + s0 + r) * ET + h * 64 + e0;
        #pragma unroll
        for (int j = 0; j < 8; j++) {
            Xs[r][e0 + j] = y[j];
            g_roll[base + j] = y[j];
        }
        __syncthreads();
    }
}

// ---------------------------------------------------------------------------
// Launcher
// ---------------------------------------------------------------------------
extern "C" void kernel_launch(void* const* d_in, const int* in_sizes, int n_in,
                              void* d_out, int out_size)
{
    const float* query = (const float*)d_in[0];
    // d_in[1] = key, d_in[2] = value  (unused by reference forward)
    const float* Wqkv  = (const float*)d_in[3];
    const float* bqkv  = (const float*)d_in[4];
    const float* Wo    = (const float*)d_in[5];
    const float* bo    = (const float*)d_in[6];
    const float* Xi    = (const float*)d_in[7];
    float* out = (float*)d_out;

    float *pqkv = nullptr, *pattn = nullptr, *proll = nullptr;
    cudaGetSymbolAddress((void**)&pqkv,  g_qkv);
    cudaGetSymbolAddress((void**)&pattn, g_attn);
    cudaGetSymbolAddress((void**)&proll, g_roll);

    // Flash attention needs > 48KB dynamic shared
    const int flash_smem = (4 * 64 * 65 + 3 * 64) * (int)sizeof(float); // ~67KB
    cudaFuncSetAttribute(flash_attn_kernel,
                         cudaFuncAttributeMaxDynamicSharedMemorySize, flash_smem);

    // 1) QKV projection: [8192,512] @ [512,1536] + bqkv
    {
        dim3 grid(3 * ET / 64, NB * LSEQ / 64);
        sgemm_bias64<<<grid, 256>>>(query, Wqkv, bqkv, pqkv,
                                    NB * LSEQ, 3 * ET, EQ);
    }

    // 2) Causal flash attention -> g_attn [b,h,s,64]
    {
        dim3 grid(LSEQ / 64, NH, NB);
        flash_attn_kernel<<<grid, 256, flash_smem>>>(pattn);
    }

    // 3) Forecast recurrence -> g_roll [b,n,s,512]
    {
        dim3 grid(LSEQ / 32, NH, NB);
        forecast_kernel<<<grid, 256>>>(Xi);
    }

    // 4) Output projection: [65536,512] @ [512,512] + bo -> d_out
    {
        dim3 grid(EQ / 64, NB * NF * LSEQ / 64);
        sgemm_bias64<<<grid, 256>>>(proll, Wo, bo, out,
                                    NB * NF * LSEQ, EQ, ET);
    }
}

// round 3
// speedup vs baseline: 1.7417x; 1.7417x over previous
#include <cuda_runtime.h>
#include <cuda_bf16.h>
#include <cstdint>

// Problem constants
#define NB   4
#define LSEQ 2048
#define EQ   512
#define ET   512
#define NH   8
#define EH   64
#define NF   8

// Scratch (device globals; allocation-free per harness rules)
__device__ float g_qkv [(size_t)NB * LSEQ * 3 * ET];   // [b, s, 1536]
__device__ float g_attn[(size_t)NB * LSEQ * ET];       // [b, s, 512] head-concat
__device__ float g_wall[(size_t)ET * NF * ET];         // [512, 4096]

// ---------------------------------------------------------------------------
// fp32 SGEMM + bias: C[M,N] = A[M,K] @ B[K,N] + bias[col & bias_mask]
// 128x128x16 tiles, 256 threads, 8x8 per thread, float4 smem loads,
// register prefetch of next K-slab.
// REMAP: write C[row, col] to out[((b*8+n)*2048+s)*512+e] with
//        b=row>>11, s=row&2047, n=col>>9, e=col&511.
// Requires M%128==0, N%128==0, K%16==0.
// ---------------------------------------------------------------------------
template<bool REMAP>
__global__ __launch_bounds__(256) void sgemm128(
    const float* __restrict__ A, const float* __restrict__ B,
    const float* __restrict__ bias, float* __restrict__ C,
    int M, int N, int K, int bias_mask)
{
    __shared__ float As[16][132];   // transposed: As[k][m]
    __shared__ float Bs[16][128];

    const int tid = threadIdx.x;
    const int tx = tid & 15;          // col group
    const int ty = tid >> 4;          // row group
    const int rowBase = blockIdx.y * 128;
    const int colBase = blockIdx.x * 128;

    // global load assignments
    const int aRow = tid >> 2;        // 0..63
    const int aCol = (tid & 3) * 4;   // 0,4,8,12
    const int bRow = tid >> 5;        // 0..7
    const int bCol = (tid & 31) * 4;  // 0..124

    const float* Aptr = A + (size_t)(rowBase + aRow) * K + aCol;
    const float* Bptr = B + (size_t)bRow * N + colBase + bCol;

    float4 a0 = *(const float4*)(Aptr);
    float4 a1 = *(const float4*)(Aptr + (size_t)64 * K);
    float4 b0 = *(const float4*)(Bptr);
    float4 b1 = *(const float4*)(Bptr + (size_t)8 * N);

    float acc[8][8] = {};
    float ar[8], br[8];

    for (int k0 = 0; k0 < K; k0 += 16) {
        // stage current regs into smem
        As[aCol + 0][aRow] = a0.x;
        As[aCol + 1][aRow] = a0.y;
        As[aCol + 2][aRow] = a0.z;
        As[aCol + 3][aRow] = a0.w;
        As[aCol + 0][64 + aRow] = a1.x;
        As[aCol + 1][64 + aRow] = a1.y;
        As[aCol + 2][64 + aRow] = a1.z;
        As[aCol + 3][64 + aRow] = a1.w;
        *(float4*)&Bs[bRow][bCol]     = b0;
        *(float4*)&Bs[bRow + 8][bCol] = b1;
        __syncthreads();

        // prefetch next K-slab (latency hidden behind compute)
        if (k0 + 16 < K) {
            a0 = *(const float4*)(Aptr + k0 + 16);
            a1 = *(const float4*)(Aptr + (size_t)64 * K + k0 + 16);
            b0 = *(const float4*)(Bptr + (size_t)(k0 + 16) * N);
            b1 = *(const float4*)(Bptr + (size_t)(k0 + 24) * N);
        }

        #pragma unroll
        for (int kk = 0; kk < 16; kk++) {
            *(float4*)&ar[0] = *(const float4*)&As[kk][ty * 4];
            *(float4*)&ar[4] = *(const float4*)&As[kk][64 + ty * 4];
            *(float4*)&br[0] = *(const float4*)&Bs[kk][tx * 4];
            *(float4*)&br[4] = *(const float4*)&Bs[kk][64 + tx * 4];
            #pragma unroll
            for (int i = 0; i < 8; i++)
                #pragma unroll
                for (int j = 0; j < 8; j++)
                    acc[i][j] += ar[i] * br[j];
        }
        __syncthreads();
    }

    // epilogue: 8 rows x 2 float4-col-groups
    #pragma unroll
    for (int i = 0; i < 8; i++) {
        int row = rowBase + ((i < 4) ? (ty * 4 + i) : (64 + ty * 4 + i - 4));
        #pragma unroll
        for (int jg = 0; jg < 2; jg++) {
            int col = colBase + jg * 64 + tx * 4;
            float4 v;
            v.x = acc[i][jg * 4 + 0] + bias[(col + 0) & bias_mask];
            v.y = acc[i][jg * 4 + 1] + bias[(col + 1) & bias_mask];
            v.z = acc[i][jg * 4 + 2] + bias[(col + 2) & bias_mask];
            v.w = acc[i][jg * 4 + 3] + bias[(col + 3) & bias_mask];
            size_t idx;
            if (REMAP) {
                int b = row >> 11, s = row & 2047;
                int n = col >> 9,  e = col & 511;
                idx = (((size_t)(b * NF + n) * LSEQ + s) * ET) + e;
            } else {
                idx = (size_t)row * N + col;
            }
            *(float4*)&C[idx] = v;
        }
    }
}

// ---------------------------------------------------------------------------
// Causal flash attention, fp32, out -> [b, s, h*64+d] concat layout.
// One block per (q_tile=64, head, batch). 256 threads.
// ---------------------------------------------------------------------------
#define NEGINF (-1e30f)

__global__ __launch_bounds__(256) void flash_attn_kernel(float* __restrict__ attn)
{
    extern __shared__ float sm[];
    float* Qs   = sm;                 // 64 x 65
    float* Ks   = Qs + 64 * 65;
    float* Vs   = Ks + 64 * 65;
    float* Ss   = Vs + 64 * 65;
    float* mrow = Ss + 64 * 65;       // 64
    float* lrow = mrow + 64;          // 64
    float* srow = lrow + 64;          // 64

    const int qt  = blockIdx.x;
    const int h   = blockIdx.y;
    const int b   = blockIdx.z;
    const int tid = threadIdx.x;
    const int tx  = tid & 15;
    const int ty  = tid >> 4;
    const int q0  = qt * 64;

    for (int i = tid; i < 64 * 64; i += 256) {
        int r = i >> 6, d = i & 63;
        Qs[r * 65 + d] = g_qkv[((size_t)(b * LSEQ + q0 + r)) * 1536 + h * 64 + d];
    }
    if (tid < 64) { mrow[tid] = NEGINF; lrow[tid] = 0.f; }

    float acc[4][4] = {};
    __syncthreads();

    for (int kt = 0; kt <= qt; kt++) {
        const int k0 = kt * 64;
        for (int i = tid; i < 64 * 64; i += 256) {
            int r = i >> 6, d = i & 63;
            size_t base = ((size_t)(b * LSEQ + k0 + r)) * 1536 + h * 64 + d;
            Ks[r * 65 + d] = g_qkv[base + 512];
            Vs[r * 65 + d] = g_qkv[base + 1024];
        }
        __syncthreads();

        // S = Q @ K^T * scale
        {
            float s[4][4] = {};
            #pragma unroll
            for (int k = 0; k < 64; k++) {
                float a[4], bv[4];
                #pragma unroll
                for (int i = 0; i < 4; i++) a[i]  = Qs[(ty * 4 + i) * 65 + k];
                #pragma unroll
                for (int j = 0; j < 4; j++) bv[j] = Ks[(tx * 4 + j) * 65 + k];
                #pragma unroll
                for (int i = 0; i < 4; i++)
                    #pragma unroll
                    for (int j = 0; j < 4; j++)
                        s[i][j] += a[i] * bv[j];
            }
            const bool diag = (kt == qt);
            #pragma unroll
            for (int i = 0; i < 4; i++) {
                int r = ty * 4 + i;
                #pragma unroll
                for (int j = 0; j < 4; j++) {
                    int c = tx * 4 + j;
                    float v = s[i][j] * 0.125f;
                    if (diag && c > r) v = NEGINF;
                    Ss[r * 65 + c] = v;
                }
            }
        }
        __syncthreads();

        // Parallel online softmax: 4 threads per row, shfl reduce within group
        {
            const int r = tid >> 2;          // 0..63
            const int q = tid & 3;           // quarter
            const int c0 = q * 16;
            float mx = NEGINF;
            #pragma unroll
            for (int c = 0; c < 16; c++) mx = fmaxf(mx, Ss[r * 65 + c0 + c]);
            mx = fmaxf(mx, __shfl_xor_sync(0xffffffffu, mx, 1));
            mx = fmaxf(mx, __shfl_xor_sync(0xffffffffu, mx, 2));
            mx = fmaxf(mx, mrow[r]);         // running max
            float sum = 0.f;
            #pragma unroll
            for (int c = 0; c < 16; c++) {
                float p = __expf(Ss[r * 65 + c0 + c] - mx);
                Ss[r * 65 + c0 + c] = p;
                sum += p;
            }
            sum += __shfl_xor_sync(0xffffffffu, sum, 1);
            sum += __shfl_xor_sync(0xffffffffu, sum, 2);
            if (q == 0) {
                float sf = __expf(mrow[r] - mx);
                mrow[r] = mx;
                lrow[r] = lrow[r] * sf + sum;
                srow[r] = sf;
            }
        }
        __syncthreads();

        // acc = acc*sf + P @ V
        {
            float o[4][4] = {};
            #pragma unroll
            for (int k = 0; k < 64; k++) {
                float a[4], bv[4];
                #pragma unroll
                for (int i = 0; i < 4; i++) a[i]  = Ss[(ty * 4 + i) * 65 + k];
                #pragma unroll
                for (int j = 0; j < 4; j++) bv[j] = Vs[k * 65 + tx * 4 + j];
                #pragma unroll
                for (int i = 0; i < 4; i++)
                    #pragma unroll
                    for (int j = 0; j < 4; j++)
                        o[i][j] += a[i] * bv[j];
            }
            #pragma unroll
            for (int i = 0; i < 4; i++) {
                float sf = srow[ty * 4 + i];
                #pragma unroll
                for (int j = 0; j < 4; j++)
                    acc[i][j] = acc[i][j] * sf + o[i][j];
            }
        }
        __syncthreads();
    }

    // Normalize, write [b, s, h*64 + d]
    #pragma unroll
    for (int i = 0; i < 4; i++) {
        int r = ty * 4 + i;
        float inv = 1.f / lrow[r];
        #pragma unroll
        for (int j = 0; j < 4; j++) {
            int c = tx * 4 + j;
            attn[((size_t)(b * LSEQ + q0 + r)) * ET + h * 64 + c] = acc[i][j] * inv;
        }
    }
}

// ---------------------------------------------------------------------------
// Weight chain: W_all[h*64+d, n*512+e] = ((I + A_h)^{n+1} @ Wo_h)[d, e]
// A_h = Xi_h - Xi_h^T. Block = (e-tile of 64, head). 256 threads, 4x4/thread.
// ---------------------------------------------------------------------------
__global__ __launch_bounds__(256) void chain_kernel(
    const float* __restrict__ Xi, const float* __restrict__ Wo,
    float* __restrict__ wall)
{
    __shared__ float Bs[64][65];
    __shared__ float Ps[2][64][65];

    const int e0 = blockIdx.x * 64;
    const int h  = blockIdx.y;
    const int tid = threadIdx.x;
    const int tx = tid & 15;
    const int ty = tid >> 4;

    for (int i = tid; i < 64 * 64; i += 256) {
        int r = i >> 6, c = i & 63;
        float v = Xi[h * 4096 + r * 64 + c] - Xi[h * 4096 + c * 64 + r];
        if (r == c) v += 1.f;
        Bs[r][c] = v;
    }
    for (int i = tid; i < 64 * 64; i += 256) {
        int r = i >> 6, c = i & 63;
        Ps[0][r][c] = Wo[(size_t)(h * 64 + r) * EQ + e0 + c];
    }
    __syncthreads();

    int cur = 0;
    for (int m = 0; m < NF; m++) {
        float t[4][4] = {};
        #pragma unroll
        for (int d = 0; d < 64; d++) {
            float a[4], bv[4];
            #pragma unroll
            for (int i = 0; i < 4; i++) a[i]  = Bs[ty * 4 + i][d];
            #pragma unroll
            for (int j = 0; j < 4; j++) bv[j] = Ps[cur][d][tx * 4 + j];
            #pragma unroll
            for (int i = 0; i < 4; i++)
                #pragma unroll
                for (int j = 0; j < 4; j++)
                    t[i][j] += a[i] * bv[j];
        }
        #pragma unroll
        for (int i = 0; i < 4; i++) {
            int r = ty * 4 + i;
            #pragma unroll
            for (int j = 0; j < 4; j++) {
                int c = tx * 4 + j;
                Ps[1 - cur][r][c] = t[i][j];
                wall[(size_t)(h * 64 + r) * (NF * ET) + m * ET + e0 + c] = t[i][j];
            }
        }
        cur ^= 1;
        __syncthreads();
    }
}

// ---------------------------------------------------------------------------
// Launcher
// ---------------------------------------------------------------------------
extern "C" void kernel_launch(void* const* d_in, const int* in_sizes, int n_in,
                              void* d_out, int out_size)
{
    const float* query = (const float*)d_in[0];
    // d_in[1]=key, d_in[2]=value (unused by reference forward)
    const float* Wqkv  = (const float*)d_in[3];
    const float* bqkv  = (const float*)d_in[4];
    const float* Wo    = (const float*)d_in[5];
    const float* bo    = (const float*)d_in[6];
    const float* Xi    = (const float*)d_in[7];
    float* out = (float*)d_out;

    float *pqkv = nullptr, *pattn = nullptr, *pwall = nullptr;
    cudaGetSymbolAddress((void**)&pqkv,  g_qkv);
    cudaGetSymbolAddress((void**)&pattn, g_attn);
    cudaGetSymbolAddress((void**)&pwall, g_wall);

    const int flash_smem = (4 * 64 * 65 + 3 * 64) * (int)sizeof(float);
    cudaFuncSetAttribute(flash_attn_kernel,
                         cudaFuncAttributeMaxDynamicSharedMemorySize, flash_smem);

    // 1) QKV projection: [8192,512] @ [512,1536] + bqkv -> g_qkv
    {
        dim3 grid((3 * ET) / 128, (NB * LSEQ) / 128);
        sgemm128<false><<<grid, 256>>>(query, Wqkv, bqkv, pqkv,
                                       NB * LSEQ, 3 * ET, EQ, 0x7fffffff);
    }

    // 2) Causal flash attention -> g_attn [b, s, 512]
    {
        dim3 grid(LSEQ / 64, NH, NB);
        flash_attn_kernel<<<grid, 256, flash_smem>>>(pattn);
    }

    // 3) Weight chain -> g_wall [512, 4096]
    {
        dim3 grid(EQ / 64, NH);
        chain_kernel<<<grid, 256>>>(Xi, Wo, pwall);
    }

    // 4) Fused forecast+output GEMM: [8192,512] @ [512,4096] + bo -> out
    {
        dim3 grid((NF * ET) / 128, (NB * LSEQ) / 128);
        sgemm128<true><<<grid, 256>>>(pattn, pwall, bo, out,
                                      NB * LSEQ, NF * ET, ET, 511);
    }
}

// round 6
// speedup vs baseline: 3.8504x; 2.2107x over previous
#include <cuda_runtime.h>
#include <cuda_bf16.h>
#include <cstdint>

// Problem constants
#define NB   4
#define LSEQ 2048
#define EQ   512
#define ET   512
#define NH   8
#define EH   64
#define NF   8

// Scratch (device globals; allocation-free per harness rules)
__device__ float g_qkv [(size_t)NB * LSEQ * 3 * ET];   // [b, s, 1536]
__device__ float g_attn[(size_t)NB * LSEQ * ET];       // [b, s, 512] head-concat
__device__ float g_wall[(size_t)ET * NF * ET];         // [512, 4096]

#define NEGINF (-1e30f)

__device__ __forceinline__ uint32_t tf32(float x) {
    uint32_t r;
    asm("cvt.rna.tf32.f32 %0, %1;" : "=r"(r) : "f"(x));
    return r;
}

__device__ __forceinline__ void mma_tf32(float* c,
    uint32_t a0, uint32_t a1, uint32_t a2, uint32_t a3,
    uint32_t b0, uint32_t b1)
{
    asm volatile(
        "mma.sync.aligned.m16n8k8.row.col.f32.tf32.tf32.f32 "
        "{%0,%1,%2,%3}, {%4,%5,%6,%7}, {%8,%9}, {%0,%1,%2,%3};"
        : "+f"(c[0]), "+f"(c[1]), "+f"(c[2]), "+f"(c[3])
        : "r"(a0), "r"(a1), "r"(a2), "r"(a3), "r"(b0), "r"(b1));
}

// ---------------------------------------------------------------------------
// tf32 tensor-core GEMM + bias: C[M,N] = A[M,K]@B[K,N] + bias[col & mask]
// 128x128x16 block tile, 8 warps (2x4), warp tile 64x32, m16n8k8 mma.
// REMAP epilogue: out[((b*8+n)*2048+s)*512+e], b=row>>11,s=row&2047,
//                 n=col>>9,e=col&511.
// Requires M%128==0, N%128==0, K%16==0.
// ---------------------------------------------------------------------------
template<bool REMAP>
__global__ __launch_bounds__(256) void tgemm128(
    const float* __restrict__ A, const float* __restrict__ B,
    const float* __restrict__ bias, float* __restrict__ C,
    int M, int N, int K, int bias_mask)
{
    __shared__ uint32_t As[128][20];   // tf32 bits, row-major, pad 20 words
    __shared__ uint32_t Bs[16][136];   // tf32 bits, [k][n], pad 136 words

    const int tid  = threadIdx.x;
    const int lane = tid & 31;
    const int wid  = tid >> 5;
    const int wm   = wid >> 2;         // 0..1
    const int wn   = wid & 3;          // 0..3
    const int g    = lane >> 2;        // 0..7
    const int qq   = lane & 3;         // 0..3
    const int rowBase = blockIdx.y * 128;
    const int colBase = blockIdx.x * 128;

    const int aRow = tid >> 2;         // 0..63
    const int aCol = (tid & 3) * 4;    // 0,4,8,12
    const int bRow = tid >> 5;         // 0..7
    const int bCol = (tid & 31) * 4;   // 0..124

    const float* Aptr = A + (size_t)(rowBase + aRow) * K + aCol;
    const float* Bptr = B + (size_t)bRow * N + colBase + bCol;

    float4 a0v = *(const float4*)(Aptr);
    float4 a1v = *(const float4*)(Aptr + (size_t)64 * K);
    float4 b0v = *(const float4*)(Bptr);
    float4 b1v = *(const float4*)(Bptr + (size_t)8 * N);

    float acc[4][4][4] = {};   // [mt][nt][frag]

    for (int k0 = 0; k0 < K; k0 += 16) {
        // stage current regs into smem, converting to tf32
        {
            uint4 t;
            t.x = tf32(a0v.x); t.y = tf32(a0v.y); t.z = tf32(a0v.z); t.w = tf32(a0v.w);
            *(uint4*)&As[aRow][aCol] = t;
            t.x = tf32(a1v.x); t.y = tf32(a1v.y); t.z = tf32(a1v.z); t.w = tf32(a1v.w);
            *(uint4*)&As[64 + aRow][aCol] = t;
            t.x = tf32(b0v.x); t.y = tf32(b0v.y); t.z = tf32(b0v.z); t.w = tf32(b0v.w);
            *(uint4*)&Bs[bRow][bCol] = t;
            t.x = tf32(b1v.x); t.y = tf32(b1v.y); t.z = tf32(b1v.z); t.w = tf32(b1v.w);
            *(uint4*)&Bs[bRow + 8][bCol] = t;
        }
        __syncthreads();

        // prefetch next K-slab
        if (k0 + 16 < K) {
            a0v = *(const float4*)(Aptr + k0 + 16);
            a1v = *(const float4*)(Aptr + (size_t)64 * K + k0 + 16);
            b0v = *(const float4*)(Bptr + (size_t)(k0 + 16) * N);
            b1v = *(const float4*)(Bptr + (size_t)(k0 + 24) * N);
        }

        #pragma unroll
        for (int k8 = 0; k8 < 16; k8 += 8) {
            uint32_t af[4][4], bf[4][2];
            #pragma unroll
            for (int mt = 0; mt < 4; mt++) {
                int r = wm * 64 + mt * 16 + g;
                af[mt][0] = As[r    ][k8 + qq];
                af[mt][1] = As[r + 8][k8 + qq];
                af[mt][2] = As[r    ][k8 + qq + 4];
                af[mt][3] = As[r + 8][k8 + qq + 4];
            }
            #pragma unroll
            for (int nt = 0; nt < 4; nt++) {
                int n = wn * 32 + nt * 8 + g;
                bf[nt][0] = Bs[k8 + qq    ][n];
                bf[nt][1] = Bs[k8 + qq + 4][n];
            }
            #pragma unroll
            for (int mt = 0; mt < 4; mt++)
                #pragma unroll
                for (int nt = 0; nt < 4; nt++)
                    mma_tf32(acc[mt][nt], af[mt][0], af[mt][1], af[mt][2], af[mt][3],
                             bf[nt][0], bf[nt][1]);
        }
        __syncthreads();
    }

    // epilogue: per frag, two float2 stores (rows r and r+8)
    #pragma unroll
    for (int mt = 0; mt < 4; mt++) {
        #pragma unroll
        for (int nt = 0; nt < 4; nt++) {
            int row = rowBase + wm * 64 + mt * 16 + g;
            int col = colBase + wn * 32 + nt * 8 + 2 * qq;
            float bx = bias[col & bias_mask];
            float by = bias[(col + 1) & bias_mask];
            float2 v0 = { acc[mt][nt][0] + bx, acc[mt][nt][1] + by };
            float2 v1 = { acc[mt][nt][2] + bx, acc[mt][nt][3] + by };
            size_t i0, i1;
            if (REMAP) {
                int n = col >> 9, e = col & 511;
                int b0i = row >> 11, s0i = row & 2047;
                i0 = (((size_t)(b0i * NF + n) * LSEQ + s0i) * ET) + e;
                int b1i = (row + 8) >> 11, s1i = (row + 8) & 2047;
                i1 = (((size_t)(b1i * NF + n) * LSEQ + s1i) * ET) + e;
            } else {
                i0 = (size_t)row * N + col;
                i1 = (size_t)(row + 8) * N + col;
            }
            *(float2*)&C[i0] = v0;
            *(float2*)&C[i1] = v1;
        }
    }
}

// ---------------------------------------------------------------------------
// Causal flash attention with tf32 mma, out -> [b, s, h*64+d].
// One block per (q_tile=64, head, batch). 256 threads, 8 warps.
// Warp w: rows (w>>1)*16..+15, cols (w&1)*32..+31 of the 64x64 tiles.
// ---------------------------------------------------------------------------
__global__ __launch_bounds__(256) void flash_attn_tf32(float* __restrict__ attn)
{
    extern __shared__ float sm[];
    float* Qs   = sm;                  // [64][68] tf32 bits (as float storage)
    float* Ks   = Qs + 64 * 68;        // [64][68] tf32 bits
    float* Vs   = Ks + 64 * 68;        // [64][72] tf32 bits
    float* Ss   = Vs + 64 * 72;        // [64][68] scores -> probs(tf32)
    float* mrow = Ss + 64 * 68;        // 64
    float* lrow = mrow + 64;           // 64
    float* srow = lrow + 64;           // 64

    const int qt  = blockIdx.x;
    const int h   = blockIdx.y;
    const int b   = blockIdx.z;
    const int tid = threadIdx.x;
    const int lane = tid & 31;
    const int wid  = tid >> 5;
    const int wm   = wid >> 1;         // 0..3
    const int wn   = wid & 1;          // 0..1
    const int g    = lane >> 2;        // 0..7
    const int qq   = lane & 3;         // 0..3
    const int q0   = qt * 64;

    // Load Q tile (tf32)
    for (int i = tid; i < 1024; i += 256) {
        int r = i >> 4, c4 = (i & 15) * 4;
        float4 v = *(const float4*)&g_qkv[((size_t)(b * LSEQ + q0 + r)) * 1536 + h * 64 + c4];
        uint32_t* dst = (uint32_t*)&Qs[r * 68 + c4];
        dst[0] = tf32(v.x); dst[1] = tf32(v.y); dst[2] = tf32(v.z); dst[3] = tf32(v.w);
    }
    if (tid < 64) { mrow[tid] = NEGINF; lrow[tid] = 0.f; }

    float acc[4][4] = {};   // O frags: [nt][frag]
    __syncthreads();

    for (int kt = 0; kt <= qt; kt++) {
        const int k0 = kt * 64;
        // Stage K, V (tf32)
        for (int i = tid; i < 1024; i += 256) {
            int r = i >> 4, c4 = (i & 15) * 4;
            size_t base = ((size_t)(b * LSEQ + k0 + r)) * 1536 + h * 64 + c4;
            float4 kv = *(const float4*)&g_qkv[base + 512];
            float4 vv = *(const float4*)&g_qkv[base + 1024];
            uint32_t* dk = (uint32_t*)&Ks[r * 68 + c4];
            dk[0] = tf32(kv.x); dk[1] = tf32(kv.y); dk[2] = tf32(kv.z); dk[3] = tf32(kv.w);
            uint32_t* dv = (uint32_t*)&Vs[r * 72 + c4];
            dv[0] = tf32(vv.x); dv[1] = tf32(vv.y); dv[2] = tf32(vv.z); dv[3] = tf32(vv.w);
        }
        __syncthreads();

        // S = Q @ K^T  (k-dim = d, 8 steps of 8)
        float s[4][4] = {};
        #pragma unroll
        for (int k8 = 0; k8 < 8; k8++) {
            const int kb = k8 * 8;
            uint32_t a0 = __float_as_uint(Qs[(wm * 16 + g    ) * 68 + kb + qq]);
            uint32_t a1 = __float_as_uint(Qs[(wm * 16 + g + 8) * 68 + kb + qq]);
            uint32_t a2 = __float_as_uint(Qs[(wm * 16 + g    ) * 68 + kb + qq + 4]);
            uint32_t a3 = __float_as_uint(Qs[(wm * 16 + g + 8) * 68 + kb + qq + 4]);
            #pragma unroll
            for (int nt = 0; nt < 4; nt++) {
                int n = wn * 32 + nt * 8 + g;   // key position
                uint32_t b0 = __float_as_uint(Ks[n * 68 + kb + qq]);
                uint32_t b1 = __float_as_uint(Ks[n * 68 + kb + qq + 4]);
                mma_tf32(s[nt], a0, a1, a2, a3, b0, b1);
            }
        }
        // write S (scale + causal mask)
        {
            const bool diag = (kt == qt);
            #pragma unroll
            for (int nt = 0; nt < 4; nt++) {
                int row = wm * 16 + g;
                int col = wn * 32 + nt * 8 + 2 * qq;
                float v0 = s[nt][0] * 0.125f;
                float v1 = s[nt][1] * 0.125f;
                float v2 = s[nt][2] * 0.125f;
                float v3 = s[nt][3] * 0.125f;
                if (diag) {
                    if (col     > row)     v0 = NEGINF;
                    if (col + 1 > row)     v1 = NEGINF;
                    if (col     > row + 8) v2 = NEGINF;
                    if (col + 1 > row + 8) v3 = NEGINF;
                }
                Ss[ row      * 68 + col    ] = v0;
                Ss[ row      * 68 + col + 1] = v1;
                Ss[(row + 8) * 68 + col    ] = v2;
                Ss[(row + 8) * 68 + col + 1] = v3;
            }
        }
        __syncthreads();

        // Online softmax: 4 threads per row; probs stored tf32-rounded
        {
            const int r  = tid >> 2;
            const int qj = tid & 3;
            const int c0 = qj * 16;
            float mx = NEGINF;
            #pragma unroll
            for (int c = 0; c < 16; c++) mx = fmaxf(mx, Ss[r * 68 + c0 + c]);
            mx = fmaxf(mx, __shfl_xor_sync(0xffffffffu, mx, 1));
            mx = fmaxf(mx, __shfl_xor_sync(0xffffffffu, mx, 2));
            mx = fmaxf(mx, mrow[r]);
            float sum = 0.f;
            #pragma unroll
            for (int c = 0; c < 16; c++) {
                float p = __expf(Ss[r * 68 + c0 + c] - mx);
                Ss[r * 68 + c0 + c] = __uint_as_float(tf32(p));
                sum += p;
            }
            sum += __shfl_xor_sync(0xffffffffu, sum, 1);
            sum += __shfl_xor_sync(0xffffffffu, sum, 2);
            if (qj == 0) {
                float sf = __expf(mrow[r] - mx);
                mrow[r] = mx;
                lrow[r] = lrow[r] * sf + sum;
                srow[r] = sf;
            }
        }
        __syncthreads();

        // rescale acc, then O += P @ V
        {
            float sf0 = srow[wm * 16 + g];
            float sf2 = srow[wm * 16 + g + 8];
            #pragma unroll
            for (int nt = 0; nt < 4; nt++) {
                acc[nt][0] *= sf0; acc[nt][1] *= sf0;
                acc[nt][2] *= sf2; acc[nt][3] *= sf2;
            }
        }
        #pragma unroll
        for (int k8 = 0; k8 < 8; k8++) {
            const int kb = k8 * 8;   // key-position chunk
            uint32_t a0 = __float_as_uint(Ss[(wm * 16 + g    ) * 68 + kb + qq]);
            uint32_t a1 = __float_as_uint(Ss[(wm * 16 + g + 8) * 68 + kb + qq]);
            uint32_t a2 = __float_as_uint(Ss[(wm * 16 + g    ) * 68 + kb + qq + 4]);
            uint32_t a3 = __float_as_uint(Ss[(wm * 16 + g + 8) * 68 + kb + qq + 4]);
            #pragma unroll
            for (int nt = 0; nt < 4; nt++) {
                int n = wn * 32 + nt * 8 + g;   // d
                uint32_t b0 = __float_as_uint(Vs[(kb + qq    ) * 72 + n]);
                uint32_t b1 = __float_as_uint(Vs[(kb + qq + 4) * 72 + n]);
                mma_tf32(acc[nt], a0, a1, a2, a3, b0, b1);
            }
        }
        __syncthreads();
    }

    // normalize + write [b, s, h*64 + d]
    {
        float inv0 = 1.f / lrow[wm * 16 + g];
        float inv2 = 1.f / lrow[wm * 16 + g + 8];
        #pragma unroll
        for (int nt = 0; nt < 4; nt++) {
            int row = wm * 16 + g;
            int col = wn * 32 + nt * 8 + 2 * qq;
            float2 v0 = { acc[nt][0] * inv0, acc[nt][1] * inv0 };
            float2 v1 = { acc[nt][2] * inv2, acc[nt][3] * inv2 };
            *(float2*)&attn[((size_t)(b * LSEQ + q0 + row    )) * ET + h * 64 + col] = v0;
            *(float2*)&attn[((size_t)(b * LSEQ + q0 + row + 8)) * ET + h * 64 + col] = v1;
        }
    }
}

// ---------------------------------------------------------------------------
// Weight chain: W_all[h*64+d, n*512+e] = ((I + A_h)^{n+1} @ Wo_h)[d, e]
// ---------------------------------------------------------------------------
__global__ __launch_bounds__(256) void chain_kernel(
    const float* __restrict__ Xi, const float* __restrict__ Wo,
    float* __restrict__ wall)
{
    __shared__ float Bs[64][65];
    __shared__ float Ps[2][64][65];

    const int e0 = blockIdx.x * 64;
    const int h  = blockIdx.y;
    const int tid = threadIdx.x;
    const int tx = tid & 15;
    const int ty = tid >> 4;

    for (int i = tid; i < 64 * 64; i += 256) {
        int r = i >> 6, c = i & 63;
        float v = Xi[h * 4096 + r * 64 + c] - Xi[h * 4096 + c * 64 + r];
        if (r == c) v += 1.f;
        Bs[r][c] = v;
    }
    for (int i = tid; i < 64 * 64; i += 256) {
        int r = i >> 6, c = i & 63;
        Ps[0][r][c] = Wo[(size_t)(h * 64 + r) * EQ + e0 + c];
    }
    __syncthreads();

    int cur = 0;
    for (int m = 0; m < NF; m++) {
        float t[4][4] = {};
        #pragma unroll
        for (int d = 0; d < 64; d++) {
            float a[4], bv[4];
            #pragma unroll
            for (int i = 0; i < 4; i++) a[i]  = Bs[ty * 4 + i][d];
            #pragma unroll
            for (int j = 0; j < 4; j++) bv[j] = Ps[cur][d][tx * 4 + j];
            #pragma unroll
            for (int i = 0; i < 4; i++)
                #pragma unroll
                for (int j = 0; j < 4; j++)
                    t[i][j] += a[i] * bv[j];
        }
        #pragma unroll
        for (int i = 0; i < 4; i++) {
            int r = ty * 4 + i;
            #pragma unroll
            for (int j = 0; j < 4; j++) {
                int c = tx * 4 + j;
                Ps[1 - cur][r][c] = t[i][j];
                wall[(size_t)(h * 64 + r) * (NF * ET) + m * ET + e0 + c] = t[i][j];
            }
        }
        cur ^= 1;
        __syncthreads();
    }
}

// ---------------------------------------------------------------------------
// Launcher
// ---------------------------------------------------------------------------
extern "C" void kernel_launch(void* const* d_in, const int* in_sizes, int n_in,
                              void* d_out, int out_size)
{
    const float* query = (const float*)d_in[0];
    // d_in[1]=key, d_in[2]=value (unused by reference forward)
    const float* Wqkv  = (const float*)d_in[3];
    const float* bqkv  = (const float*)d_in[4];
    const float* Wo    = (const float*)d_in[5];
    const float* bo    = (const float*)d_in[6];
    const float* Xi    = (const float*)d_in[7];
    float* out = (float*)d_out;

    float *pqkv = nullptr, *pattn = nullptr, *pwall = nullptr;
    cudaGetSymbolAddress((void**)&pqkv,  g_qkv);
    cudaGetSymbolAddress((void**)&pattn, g_attn);
    cudaGetSymbolAddress((void**)&pwall, g_wall);

    // flash smem: Qs(64*68) + Ks(64*68) + Vs(64*72) + Ss(64*68) + 3*64 floats
    const int flash_smem = (64 * 68 * 3 + 64 * 72 + 3 * 64) * (int)sizeof(float); // 71424
    cudaFuncSetAttribute(flash_attn_tf32,
                         cudaFuncAttributeMaxDynamicSharedMemorySize, flash_smem);

    // 1) QKV projection: [8192,512] @ [512,1536] + bqkv -> g_qkv
    {
        dim3 grid((3 * ET) / 128, (NB * LSEQ) / 128);
        tgemm128<false><<<grid, 256>>>(query, Wqkv, bqkv, pqkv,
                                       NB * LSEQ, 3 * ET, EQ, 0x7fffffff);
    }

    // 2) Causal flash attention -> g_attn [b, s, 512]
    {
        dim3 grid(LSEQ / 64, NH, NB);
        flash_attn_tf32<<<grid, 256, flash_smem>>>(pattn);
    }

    // 3) Weight chain -> g_wall [512, 4096]
    {
        dim3 grid(EQ / 64, NH);
        chain_kernel<<<grid, 256>>>(Xi, Wo, pwall);
    }

    // 4) Fused forecast+output GEMM: [8192,512] @ [512,4096] + bo -> out
    {
        dim3 grid((NF * ET) / 128, (NB * LSEQ) / 128);
        tgemm128<true><<<grid, 256>>>(pattn, pwall, bo, out,
                                      NB * LSEQ, NF * ET, ET, 511);
    }
}